// round 7
// baseline (speedup 1.0000x reference)
#include <cuda_runtime.h>

// Shapes fixed by reference setup_inputs()
#define BB      16
#define NPTS    1024          // H*W
#define DD      128           // = 32 float4 chunks
#define KK      32
#define GPB     16            // chunks (CTAs) per batch
#define PPB     (NPTS / GPB)  // 64 points per CTA
#define NTHREADS 256
#define NCHUNK  (BB * GPB)    // 256

// Shared layout: xs[64][33] f4 | cs[32][34] f4 | As[64][33] f | x2s[64] f
#define XS_STRIDE 33
#define CS_STRIDE 34
#define AS_STRIDE 33
#define XS_BYTES  (PPB * XS_STRIDE * 16)            // 33792
#define CS_BYTES  (KK * CS_STRIDE * 16)             // 17408
#define AS_BYTES  (PPB * AS_STRIDE * 4)             // 8448
#define SMEM_BYTES (XS_BYTES + CS_BYTES + AS_BYTES + PPB * 4)  // 59904

// Cross-CTA partial tiles: [chunk][d][k] (coalesced STG over k; reduce loads float4 over k)
__device__ float4 g_Ep4[NCHUNK * KK * DD / 4];      // 4 MB scratch

__device__ __forceinline__ unsigned long long ffma2_(unsigned long long a,
                                                     unsigned long long b,
                                                     unsigned long long c) {
    unsigned long long d;
    asm("fma.rn.f32x2 %0, %1, %2, %3;" : "=l"(d) : "l"(a), "l"(b), "l"(c));
    return d;
}
__device__ __forceinline__ unsigned long long pack2(float lo, float hi) {
    unsigned long long r;
    asm("mov.b64 %0, {%1, %2};" : "=l"(r) : "f"(lo), "f"(hi));
    return r;
}
__device__ __forceinline__ float2 unpack2(unsigned long long v) {
    float2 r;
    asm("mov.b64 {%0, %1}, %2;" : "=f"(r.x), "=f"(r.y) : "l"(v));
    return r;
}

__global__ __launch_bounds__(NTHREADS, 2)
void ev_encode_kernel(const float* __restrict__ x,
                      const float* __restrict__ cw,
                      const float* __restrict__ scale) {
    extern __shared__ char sraw[];
    float4* xs  = (float4*)sraw;                          // [PPB][33]
    float4* cs  = (float4*)(sraw + XS_BYTES);             // [KK][34] rotated
    float*  As  = (float*)(sraw + XS_BYTES + CS_BYTES);   // [PPB][33]
    float*  x2s = As + PPB * AS_STRIDE;                   // [PPB]

    const int t    = threadIdx.x;
    const int lane = t & 31;
    const int w    = t >> 5;              // 0..7
    const int b    = blockIdx.x >> 4;
    const int g    = blockIdx.x & 15;
    const int mi   = lane & 1;            // point-subgroup (2 x 4 pts)
    const int ni   = lane >> 1;           // k-pair index (16 pairs)

    // ---- Phase A1: stage x tile; warp w loads complete rows w, w+8, ...
    //      chunk = lane -> fold ||x||^2 reduction into the staging pass ----
    const float4* xg = (const float4*)(x + ((size_t)b * NPTS + (size_t)g * PPB) * DD);
    #pragma unroll
    for (int i = 0; i < 8; ++i) {
        int p = w + 8 * i;
        float4 v = xg[p * 32 + lane];
        xs[p * XS_STRIDE + lane] = v;
        float s2 = v.x * v.x + v.y * v.y + v.z * v.z + v.w * v.w;
        #pragma unroll
        for (int o = 16; o; o >>= 1) s2 += __shfl_xor_sync(0xffffffffu, s2, o);
        if (lane == 0) x2s[p] = s2;
    }

    // ---- Phase A2: augmented codewords w_k = -2*s_k*c_k at slot (d4 + k/2)&31;
    //      slot 32 = (s_k, s_k*||c_k||^2, 0, 0). Warp w builds rows 4w..4w+3. ----
    #pragma unroll
    for (int j = 0; j < 4; ++j) {
        int k = w * 4 + j;
        float4 c = ((const float4*)cw)[k * 32 + lane];
        float s  = scale[k];
        float c2 = c.x * c.x + c.y * c.y + c.z * c.z + c.w * c.w;
        #pragma unroll
        for (int o = 16; o; o >>= 1) c2 += __shfl_xor_sync(0xffffffffu, c2, o);
        float m2 = -2.f * s;
        cs[k * CS_STRIDE + ((lane + (k >> 1)) & 31)] =
            make_float4(m2 * c.x, m2 * c.y, m2 * c.z, m2 * c.w);
        if (lane == 0)
            cs[k * CS_STRIDE + 32] = make_float4(s, s * c2, 0.f, 0.f);
    }
    __syncthreads();

    // ---- Phase C: stage-1 GEMM (logits), 4 pts x 2 k per lane, folded accs ----
    unsigned long long acc[4][2];
    #pragma unroll
    for (int p = 0; p < 4; ++p) { acc[p][0] = 0ull; acc[p][1] = 0ull; }

    const int pbase = w * 8 + mi * 4;
    const ulonglong2* xs2 = (const ulonglong2*)xs;
    const ulonglong2* csrow0 = (const ulonglong2*)cs + (2 * ni + 0) * CS_STRIDE;
    const ulonglong2* csrow1 = (const ulonglong2*)cs + (2 * ni + 1) * CS_STRIDE;

    #pragma unroll 8
    for (int d4 = 0; d4 < 32; ++d4) {
        int cslot = (d4 + ni) & 31;
        ulonglong2 cv0 = csrow0[cslot];
        ulonglong2 cv1 = csrow1[cslot];
        #pragma unroll
        for (int p = 0; p < 4; ++p) {
            ulonglong2 xv = xs2[(pbase + p) * XS_STRIDE + d4];   // linear in d4
            acc[p][0] = ffma2_(cv0.x, xv.x, acc[p][0]);
            acc[p][0] = ffma2_(cv0.y, xv.y, acc[p][0]);
            acc[p][1] = ffma2_(cv1.x, xv.x, acc[p][1]);
            acc[p][1] = ffma2_(cv1.y, xv.y, acc[p][1]);
        }
    }

    float4 cc0 = cs[(2 * ni + 0) * CS_STRIDE + 32];   // (s, s*c2, 0, 0)
    float4 cc1 = cs[(2 * ni + 1) * CS_STRIDE + 32];

    // ---- softmax over K=32 (butterfly on ni bits; mi bit untouched) ----
    #pragma unroll
    for (int p = 0; p < 4; ++p) {
        float x2 = x2s[pbase + p];                     // broadcast LDS
        float2 u0 = unpack2(acc[p][0]);
        float2 u1 = unpack2(acc[p][1]);
        float SL0 = (u0.x + u0.y) + fmaf(cc0.x, x2, cc0.y);
        float SL1 = (u1.x + u1.y) + fmaf(cc1.x, x2, cc1.y);
        float m = fmaxf(SL0, SL1);
        #pragma unroll
        for (int o = 2; o <= 16; o <<= 1) m = fmaxf(m, __shfl_xor_sync(0xffffffffu, m, o));
        float e0 = __expf(SL0 - m);
        float e1 = __expf(SL1 - m);
        float ssum = e0 + e1;
        #pragma unroll
        for (int o = 2; o <= 16; o <<= 1) ssum += __shfl_xor_sync(0xffffffffu, ssum, o);
        float inv = 1.f / ssum;
        As[(pbase + p) * AS_STRIDE + 2 * ni + 0] = e0 * inv;
        As[(pbase + p) * AS_STRIDE + 2 * ni + 1] = e1 * inv;
    }
    __syncthreads();

    // ---- Phase D: E[k][d] = sum_p A[p][k]*x[p][d]; lane=k, warp owns 16 d ----
    unsigned long long acc2[8];
    #pragma unroll
    for (int q = 0; q < 8; ++q) acc2[q] = 0ull;
    float sA = 0.f;
    const int d4b = w * 4;

    #pragma unroll 8
    for (int p = 0; p < PPB; ++p) {
        float a = As[p * AS_STRIDE + lane];            // conflict-free (stride 33)
        sA += a;
        unsigned long long a2 = pack2(a, a);
        #pragma unroll
        for (int q = 0; q < 4; ++q) {
            ulonglong2 xv = xs2[p * XS_STRIDE + d4b + q];   // uniform -> broadcast
            acc2[2 * q + 0] = ffma2_(a2, xv.x, acc2[2 * q + 0]);
            acc2[2 * q + 1] = ffma2_(a2, xv.y, acc2[2 * q + 1]);
        }
    }

    // ---- epilogue: partial tile -> g_Ep[chunk][d][k], coalesced STG.32 over k ----
    float* ep = (float*)g_Ep4 + (size_t)blockIdx.x * (KK * DD);
    const float4* crow = (const float4*)(cw + (size_t)lane * DD);
    #pragma unroll
    for (int q = 0; q < 4; ++q) {
        int d4 = d4b + q;
        float4 c = crow[d4];
        float2 lo = unpack2(acc2[2 * q + 0]);
        float2 hi = unpack2(acc2[2 * q + 1]);
        ep[(4 * d4 + 0) * KK + lane] = fmaf(-sA, c.x, lo.x);
        ep[(4 * d4 + 1) * KK + lane] = fmaf(-sA, c.y, lo.y);
        ep[(4 * d4 + 2) * KK + lane] = fmaf(-sA, c.z, hi.x);
        ep[(4 * d4 + 3) * KK + lane] = fmaf(-sA, c.w, hi.y);
    }
}

// out[b][k][d] = sum_{c=0..15} g_Ep[b*16+c][d][k]
// One warp per (b,d). Lane = (cgrp, k4): lane sums 4 chunks, shfl-tree folds cgrp.
__global__ __launch_bounds__(NTHREADS)
void ev_reduce_kernel(float* __restrict__ out) {
    const int lane   = threadIdx.x & 31;
    const int warpId = (blockIdx.x << 3) | (threadIdx.x >> 5);   // 0..2047
    const int b  = warpId >> 7;          // 0..15
    const int d  = warpId & 127;         // 0..127
    const int k4 = lane & 7;             // float4 group over k
    const int cg = lane >> 3;            // chunk group (4 chunks each)

    // float4 index within a chunk tile: d*8 + k4 ; chunk tile = 1024 float4
    const float4* base = g_Ep4 + ((size_t)(b * GPB + cg * 4)) * (KK * DD / 4)
                       + (size_t)d * (KK / 4) + k4;
    float4 s = make_float4(0.f, 0.f, 0.f, 0.f);
    #pragma unroll
    for (int j = 0; j < 4; ++j) {
        float4 v = base[(size_t)j * (KK * DD / 4)];   // 4x128B segments / warp
        s.x += v.x; s.y += v.y; s.z += v.z; s.w += v.w;
    }
    // fold the 4 chunk-groups (lane bits 3,4)
    #pragma unroll
    for (int o = 8; o <= 16; o <<= 1) {
        s.x += __shfl_xor_sync(0xffffffffu, s.x, o);
        s.y += __shfl_xor_sync(0xffffffffu, s.y, o);
        s.z += __shfl_xor_sync(0xffffffffu, s.z, o);
        s.w += __shfl_xor_sync(0xffffffffu, s.w, o);
    }
    if (cg == 0) {
        float* ob = out + ((size_t)b * KK + 4 * k4) * DD + d;
        ob[0 * DD] = s.x;
        ob[1 * DD] = s.y;
        ob[2 * DD] = s.z;
        ob[3 * DD] = s.w;
    }
}

extern "C" void kernel_launch(void* const* d_in, const int* in_sizes, int n_in,
                              void* d_out, int out_size) {
    const float* x  = (const float*)d_in[0];   // [16,32,32,128]
    const float* cw = (const float*)d_in[1];   // [32,128]
    const float* sc = (const float*)d_in[2];   // [32]
    float* out = (float*)d_out;                // [16,32,128]

    cudaFuncSetAttribute(ev_encode_kernel,
                         cudaFuncAttributeMaxDynamicSharedMemorySize, SMEM_BYTES);

    ev_encode_kernel<<<NCHUNK, NTHREADS, SMEM_BYTES>>>(x, cw, sc);
    // one warp per (b,d) pair: BB*DD warps / 8 warps per CTA = 256 CTAs
    ev_reduce_kernel<<<(BB * DD) / 8, NTHREADS>>>(out);
}

// round 8
// speedup vs baseline: 1.5341x; 1.5341x over previous
#include <cuda_runtime.h>

// Shapes fixed by reference setup_inputs()
#define BB      16
#define NPTS    1024          // H*W
#define DD      128           // = 32 float4 chunks
#define KK      32
#define GPB     16            // chunks (CTAs) per batch
#define PPB     (NPTS / GPB)  // 64 points per CTA
#define NTHREADS 256
#define NCHUNK  (BB * GPB)    // 256

// Shared layout: xs[64][33] f4 | cs[32][34] f4 | As[64][33] f | x2s[64] f
#define XS_STRIDE 33
#define CS_STRIDE 34
#define AS_STRIDE 33
#define XS_BYTES  (PPB * XS_STRIDE * 16)            // 33792
#define CS_BYTES  (KK * CS_STRIDE * 16)             // 17408
#define AS_BYTES  (PPB * AS_STRIDE * 4)             // 8448
#define SMEM_BYTES (XS_BYTES + CS_BYTES + AS_BYTES + PPB * 4)  // 59904

__device__ __forceinline__ unsigned long long ffma2_(unsigned long long a,
                                                     unsigned long long b,
                                                     unsigned long long c) {
    unsigned long long d;
    asm("fma.rn.f32x2 %0, %1, %2, %3;" : "=l"(d) : "l"(a), "l"(b), "l"(c));
    return d;
}
__device__ __forceinline__ unsigned long long pack2(float lo, float hi) {
    unsigned long long r;
    asm("mov.b64 %0, {%1, %2};" : "=l"(r) : "f"(lo), "f"(hi));
    return r;
}
__device__ __forceinline__ float2 unpack2(unsigned long long v) {
    float2 r;
    asm("mov.b64 {%0, %1}, %2;" : "=f"(r.x), "=f"(r.y) : "l"(v));
    return r;
}
// Vector reduction: fire-and-forget float4 add to global (PTX ISA 8.1+, sm_90+)
__device__ __forceinline__ void red_add_v4(float* p, float a, float b, float c, float d) {
    asm volatile("red.global.add.v4.f32 [%0], {%1, %2, %3, %4};"
                 :: "l"(p), "f"(a), "f"(b), "f"(c), "f"(d) : "memory");
}

__global__ void ev_zero_kernel(float4* __restrict__ out) {
    out[blockIdx.x * 256 + threadIdx.x] = make_float4(0.f, 0.f, 0.f, 0.f);
}

__global__ __launch_bounds__(NTHREADS, 2)
void ev_encode_kernel(const float* __restrict__ x,
                      const float* __restrict__ cw,
                      const float* __restrict__ scale,
                      float* __restrict__ out) {
    extern __shared__ char sraw[];
    float4* xs  = (float4*)sraw;                          // [PPB][33]
    float4* cs  = (float4*)(sraw + XS_BYTES);             // [KK][34] rotated
    float*  As  = (float*)(sraw + XS_BYTES + CS_BYTES);   // [PPB][33]
    float*  x2s = As + PPB * AS_STRIDE;                   // [PPB]

    const int t    = threadIdx.x;
    const int lane = t & 31;
    const int w    = t >> 5;              // 0..7
    const int b    = blockIdx.x >> 4;
    const int g    = blockIdx.x & 15;
    const int mi   = lane & 1;            // point-subgroup (2 x 4 pts)
    const int ni   = lane >> 1;           // k-pair index (16 pairs)

    // ---- Phase A1: stage x tile; warp w loads complete rows w, w+8, ...
    //      chunk = lane -> fold ||x||^2 reduction into the staging pass ----
    const float4* xg = (const float4*)(x + ((size_t)b * NPTS + (size_t)g * PPB) * DD);
    #pragma unroll
    for (int i = 0; i < 8; ++i) {
        int p = w + 8 * i;
        float4 v = xg[p * 32 + lane];
        xs[p * XS_STRIDE + lane] = v;
        float s2 = v.x * v.x + v.y * v.y + v.z * v.z + v.w * v.w;
        #pragma unroll
        for (int o = 16; o; o >>= 1) s2 += __shfl_xor_sync(0xffffffffu, s2, o);
        if (lane == 0) x2s[p] = s2;
    }

    // ---- Phase A2: augmented codewords w_k = -2*s_k*c_k at slot (d4 + k/2)&31;
    //      slot 32 = (s_k, s_k*||c_k||^2, 0, 0). Warp w builds rows 4w..4w+3. ----
    #pragma unroll
    for (int j = 0; j < 4; ++j) {
        int k = w * 4 + j;
        float4 c = ((const float4*)cw)[k * 32 + lane];
        float s  = scale[k];
        float c2 = c.x * c.x + c.y * c.y + c.z * c.z + c.w * c.w;
        #pragma unroll
        for (int o = 16; o; o >>= 1) c2 += __shfl_xor_sync(0xffffffffu, c2, o);
        float m2 = -2.f * s;
        cs[k * CS_STRIDE + ((lane + (k >> 1)) & 31)] =
            make_float4(m2 * c.x, m2 * c.y, m2 * c.z, m2 * c.w);
        if (lane == 0)
            cs[k * CS_STRIDE + 32] = make_float4(s, s * c2, 0.f, 0.f);
    }
    __syncthreads();

    // ---- Phase C: stage-1 GEMM (logits), 4 pts x 2 k per lane, folded accs ----
    unsigned long long acc[4][2];
    #pragma unroll
    for (int p = 0; p < 4; ++p) { acc[p][0] = 0ull; acc[p][1] = 0ull; }

    const int pbase = w * 8 + mi * 4;
    const ulonglong2* xs2 = (const ulonglong2*)xs;
    const ulonglong2* csrow0 = (const ulonglong2*)cs + (2 * ni + 0) * CS_STRIDE;
    const ulonglong2* csrow1 = (const ulonglong2*)cs + (2 * ni + 1) * CS_STRIDE;

    #pragma unroll 8
    for (int d4 = 0; d4 < 32; ++d4) {
        int cslot = (d4 + ni) & 31;
        ulonglong2 cv0 = csrow0[cslot];
        ulonglong2 cv1 = csrow1[cslot];
        #pragma unroll
        for (int p = 0; p < 4; ++p) {
            ulonglong2 xv = xs2[(pbase + p) * XS_STRIDE + d4];   // linear in d4
            acc[p][0] = ffma2_(cv0.x, xv.x, acc[p][0]);
            acc[p][0] = ffma2_(cv0.y, xv.y, acc[p][0]);
            acc[p][1] = ffma2_(cv1.x, xv.x, acc[p][1]);
            acc[p][1] = ffma2_(cv1.y, xv.y, acc[p][1]);
        }
    }

    float4 cc0 = cs[(2 * ni + 0) * CS_STRIDE + 32];   // (s, s*c2, 0, 0)
    float4 cc1 = cs[(2 * ni + 1) * CS_STRIDE + 32];

    // ---- softmax over K=32 (butterfly on ni bits; mi bit untouched) ----
    #pragma unroll
    for (int p = 0; p < 4; ++p) {
        float x2 = x2s[pbase + p];                     // broadcast LDS
        float2 u0 = unpack2(acc[p][0]);
        float2 u1 = unpack2(acc[p][1]);
        float SL0 = (u0.x + u0.y) + fmaf(cc0.x, x2, cc0.y);
        float SL1 = (u1.x + u1.y) + fmaf(cc1.x, x2, cc1.y);
        float m = fmaxf(SL0, SL1);
        #pragma unroll
        for (int o = 2; o <= 16; o <<= 1) m = fmaxf(m, __shfl_xor_sync(0xffffffffu, m, o));
        float e0 = __expf(SL0 - m);
        float e1 = __expf(SL1 - m);
        float ssum = e0 + e1;
        #pragma unroll
        for (int o = 2; o <= 16; o <<= 1) ssum += __shfl_xor_sync(0xffffffffu, ssum, o);
        float inv = 1.f / ssum;
        As[(pbase + p) * AS_STRIDE + 2 * ni + 0] = e0 * inv;
        As[(pbase + p) * AS_STRIDE + 2 * ni + 1] = e1 * inv;
    }
    __syncthreads();

    // ---- Phase D: E[k][d] = sum_p A[p][k]*x[p][d]; lane=k, warp owns 16 d ----
    unsigned long long acc2[8];
    #pragma unroll
    for (int q = 0; q < 8; ++q) acc2[q] = 0ull;
    float sA = 0.f;
    const int d4b = w * 4;

    #pragma unroll 8
    for (int p = 0; p < PPB; ++p) {
        float a = As[p * AS_STRIDE + lane];            // conflict-free (stride 33)
        sA += a;
        unsigned long long a2 = pack2(a, a);
        #pragma unroll
        for (int q = 0; q < 4; ++q) {
            ulonglong2 xv = xs2[p * XS_STRIDE + d4b + q];   // uniform -> broadcast
            acc2[2 * q + 0] = ffma2_(a2, xv.x, acc2[2 * q + 0]);
            acc2[2 * q + 1] = ffma2_(a2, xv.y, acc2[2 * q + 1]);
        }
    }

    // ---- epilogue: fire-and-forget vector reductions straight into out ----
    float* ob = out + ((size_t)b * KK + lane) * DD;
    const float4* crow = (const float4*)(cw + (size_t)lane * DD);
    #pragma unroll
    for (int q = 0; q < 4; ++q) {
        int d4 = d4b + q;
        float4 c = crow[d4];
        float2 lo = unpack2(acc2[2 * q + 0]);
        float2 hi = unpack2(acc2[2 * q + 1]);
        red_add_v4(ob + 4 * d4,
                   fmaf(-sA, c.x, lo.x),
                   fmaf(-sA, c.y, lo.y),
                   fmaf(-sA, c.z, hi.x),
                   fmaf(-sA, c.w, hi.y));
    }
}

extern "C" void kernel_launch(void* const* d_in, const int* in_sizes, int n_in,
                              void* d_out, int out_size) {
    const float* x  = (const float*)d_in[0];   // [16,32,32,128]
    const float* cw = (const float*)d_in[1];   // [32,128]
    const float* sc = (const float*)d_in[2];   // [32]
    float* out = (float*)d_out;                // [16,32,128]

    cudaFuncSetAttribute(ev_encode_kernel,
                         cudaFuncAttributeMaxDynamicSharedMemorySize, SMEM_BYTES);

    // out is poisoned by the harness; REDs need zeros
    ev_zero_kernel<<<(BB * KK * DD / 4) / 256, 256>>>((float4*)out);
    ev_encode_kernel<<<NCHUNK, NTHREADS, SMEM_BYTES>>>(x, cw, sc, out);
}

// round 9
// speedup vs baseline: 1.6804x; 1.0953x over previous
#include <cuda_runtime.h>

// Shapes fixed by reference setup_inputs()
#define BB      16
#define NPTS    1024          // H*W
#define DD      128           // = 32 float4 chunks
#define KK      32
#define GPB     16            // chunks (CTAs) per batch
#define PPB     (NPTS / GPB)  // 64 points per CTA
#define NTHREADS 256
#define NCHUNK  (BB * GPB)    // 256

// Shared layout: xs[64][33] f4 | cs[32][34] f4 | Ad[64][17] f4 (dup pairs) | x2s[64] f
#define XS_STRIDE 33
#define CS_STRIDE 34
#define AD_STRIDE 17          // float4 units per point-row: 16 used (32 k dup'd) + 1 pad
#define XS_BYTES  (PPB * XS_STRIDE * 16)            // 33792
#define CS_BYTES  (KK * CS_STRIDE * 16)             // 17408
#define AD_BYTES  (PPB * AD_STRIDE * 16)            // 17408
#define SMEM_BYTES (XS_BYTES + CS_BYTES + AD_BYTES + PPB * 4)  // 68864

__device__ __forceinline__ unsigned long long ffma2_(unsigned long long a,
                                                     unsigned long long b,
                                                     unsigned long long c) {
    unsigned long long d;
    asm("fma.rn.f32x2 %0, %1, %2, %3;" : "=l"(d) : "l"(a), "l"(b), "l"(c));
    return d;
}
__device__ __forceinline__ float2 unpack2(unsigned long long v) {
    float2 r;
    asm("mov.b64 {%0, %1}, %2;" : "=f"(r.x), "=f"(r.y) : "l"(v));
    return r;
}
// Vector reduction: fire-and-forget float4 add to global (sm_90+)
__device__ __forceinline__ void red_add_v4(float* p, float a, float b, float c, float d) {
    asm volatile("red.global.add.v4.f32 [%0], {%1, %2, %3, %4};"
                 :: "l"(p), "f"(a), "f"(b), "f"(c), "f"(d) : "memory");
}

__global__ void ev_zero_kernel(float4* __restrict__ out) {
    out[blockIdx.x * 256 + threadIdx.x] = make_float4(0.f, 0.f, 0.f, 0.f);
}

__global__ __launch_bounds__(NTHREADS, 2)
void ev_encode_kernel(const float* __restrict__ x,
                      const float* __restrict__ cw,
                      const float* __restrict__ scale,
                      float* __restrict__ out) {
    extern __shared__ char sraw[];
    float4* xs  = (float4*)sraw;                          // [PPB][33]
    float4* cs  = (float4*)(sraw + XS_BYTES);             // [KK][34] rotated
    float4* Ad4 = (float4*)(sraw + XS_BYTES + CS_BYTES);  // [PPB][17]: (a0,a0,a1,a1)
    float*  x2s = (float*)(sraw + XS_BYTES + CS_BYTES + AD_BYTES);  // [PPB]

    const int t    = threadIdx.x;
    const int lane = t & 31;
    const int w    = t >> 5;              // 0..7
    const int b    = blockIdx.x >> 4;
    const int g    = blockIdx.x & 15;
    const int mi   = lane & 1;            // point-subgroup (2 x 4 pts)
    const int ni   = lane >> 1;           // k-pair index (16 pairs)

    // ---- Phase A1: stage x tile; warp w loads complete rows w, w+8, ...
    //      chunk = lane -> fold ||x||^2 reduction into the staging pass ----
    const float4* xg = (const float4*)(x + ((size_t)b * NPTS + (size_t)g * PPB) * DD);
    #pragma unroll
    for (int i = 0; i < 8; ++i) {
        int p = w + 8 * i;
        float4 v = xg[p * 32 + lane];
        xs[p * XS_STRIDE + lane] = v;
        float s2 = v.x * v.x + v.y * v.y + v.z * v.z + v.w * v.w;
        #pragma unroll
        for (int o = 16; o; o >>= 1) s2 += __shfl_xor_sync(0xffffffffu, s2, o);
        if (lane == 0) x2s[p] = s2;
    }

    // ---- Phase A2: augmented codewords w_k = -2*s_k*c_k at slot (d4 + k/2)&31;
    //      slot 32 = (s_k, s_k*||c_k||^2, 0, 0). Warp w builds rows 4w..4w+3. ----
    #pragma unroll
    for (int j = 0; j < 4; ++j) {
        int k = w * 4 + j;
        float4 c = ((const float4*)cw)[k * 32 + lane];
        float s  = scale[k];
        float c2 = c.x * c.x + c.y * c.y + c.z * c.z + c.w * c.w;
        #pragma unroll
        for (int o = 16; o; o >>= 1) c2 += __shfl_xor_sync(0xffffffffu, c2, o);
        float m2 = -2.f * s;
        cs[k * CS_STRIDE + ((lane + (k >> 1)) & 31)] =
            make_float4(m2 * c.x, m2 * c.y, m2 * c.z, m2 * c.w);
        if (lane == 0)
            cs[k * CS_STRIDE + 32] = make_float4(s, s * c2, 0.f, 0.f);
    }
    __syncthreads();

    // ---- Phase C: stage-1 GEMM (logits), 4 pts x 2 k per lane, folded accs ----
    unsigned long long acc[4][2];
    #pragma unroll
    for (int p = 0; p < 4; ++p) { acc[p][0] = 0ull; acc[p][1] = 0ull; }

    const int pbase = w * 8 + mi * 4;
    const ulonglong2* xs2 = (const ulonglong2*)xs;
    const ulonglong2* csrow0 = (const ulonglong2*)cs + (2 * ni + 0) * CS_STRIDE;
    const ulonglong2* csrow1 = (const ulonglong2*)cs + (2 * ni + 1) * CS_STRIDE;

    #pragma unroll 8
    for (int d4 = 0; d4 < 32; ++d4) {
        int cslot = (d4 + ni) & 31;
        ulonglong2 cv0 = csrow0[cslot];
        ulonglong2 cv1 = csrow1[cslot];
        #pragma unroll
        for (int p = 0; p < 4; ++p) {
            ulonglong2 xv = xs2[(pbase + p) * XS_STRIDE + d4];   // linear in d4
            acc[p][0] = ffma2_(cv0.x, xv.x, acc[p][0]);
            acc[p][0] = ffma2_(cv0.y, xv.y, acc[p][0]);
            acc[p][1] = ffma2_(cv1.x, xv.x, acc[p][1]);
            acc[p][1] = ffma2_(cv1.y, xv.y, acc[p][1]);
        }
    }

    float4 cc0 = cs[(2 * ni + 0) * CS_STRIDE + 32];   // (s, s*c2, 0, 0)
    float4 cc1 = cs[(2 * ni + 1) * CS_STRIDE + 32];

    // ---- softmax over K=32 (butterfly on ni bits; mi bit untouched) ----
    //      store A pre-duplicated: Ad[pt][ni] = (a_{2ni}, a_{2ni}, a_{2ni+1}, a_{2ni+1})
    #pragma unroll
    for (int p = 0; p < 4; ++p) {
        float x2 = x2s[pbase + p];                     // broadcast LDS
        float2 u0 = unpack2(acc[p][0]);
        float2 u1 = unpack2(acc[p][1]);
        float SL0 = (u0.x + u0.y) + fmaf(cc0.x, x2, cc0.y);
        float SL1 = (u1.x + u1.y) + fmaf(cc1.x, x2, cc1.y);
        float m = fmaxf(SL0, SL1);
        #pragma unroll
        for (int o = 2; o <= 16; o <<= 1) m = fmaxf(m, __shfl_xor_sync(0xffffffffu, m, o));
        float e0 = __expf(SL0 - m);
        float e1 = __expf(SL1 - m);
        float ssum = e0 + e1;
        #pragma unroll
        for (int o = 2; o <= 16; o <<= 1) ssum += __shfl_xor_sync(0xffffffffu, ssum, o);
        float inv = 1.f / ssum;
        float a0 = e0 * inv, a1 = e1 * inv;
        Ad4[(pbase + p) * AD_STRIDE + ni] = make_float4(a0, a0, a1, a1);  // 1 STS.128
    }
    __syncthreads();

    // ---- Phase D: E[k][d] = sum_p A[p][k]*x[p][d] ----
    //      warp w owns k-group kg=4w..4w+3; lane owns d-chunk d4=lane (4 d).
    //      Per point: 1 distinct LDS.128 (x row slice) + 2 broadcast LDS.128 (A dup).
    unsigned long long acc2[8];
    #pragma unroll
    for (int q = 0; q < 8; ++q) acc2[q] = 0ull;
    const int kg = 4 * w;
    const ulonglong2* Ad2 = (const ulonglong2*)Ad4;

    #pragma unroll 8
    for (int p = 0; p < PPB; ++p) {
        ulonglong2 xv  = xs2[p * XS_STRIDE + lane];        // distinct, conflict-free
        ulonglong2 a01 = Ad2[p * AD_STRIDE + 2 * w];       // (a0,a0),(a1,a1)  bcast
        ulonglong2 a23 = Ad2[p * AD_STRIDE + 2 * w + 1];   // (a2,a2),(a3,a3)  bcast
        acc2[0] = ffma2_(a01.x, xv.x, acc2[0]);
        acc2[1] = ffma2_(a01.x, xv.y, acc2[1]);
        acc2[2] = ffma2_(a01.y, xv.x, acc2[2]);
        acc2[3] = ffma2_(a01.y, xv.y, acc2[3]);
        acc2[4] = ffma2_(a23.x, xv.x, acc2[4]);
        acc2[5] = ffma2_(a23.x, xv.y, acc2[5]);
        acc2[6] = ffma2_(a23.y, xv.x, acc2[6]);
        acc2[7] = ffma2_(a23.y, xv.y, acc2[7]);
    }

    // ---- sA_j = sum_p A[p][kg+j]: lane-parallel partials + warp butterfly ----
    float4 sa = make_float4(0.f, 0.f, 0.f, 0.f);
    #pragma unroll
    for (int h = 0; h < 2; ++h) {
        int p = lane + 32 * h;
        float4 u = Ad4[p * AD_STRIDE + 2 * w];       // a0,a0,a1,a1
        float4 v = Ad4[p * AD_STRIDE + 2 * w + 1];   // a2,a2,a3,a3
        sa.x += u.x; sa.y += u.z; sa.z += v.x; sa.w += v.z;
    }
    #pragma unroll
    for (int o = 16; o; o >>= 1) {
        sa.x += __shfl_xor_sync(0xffffffffu, sa.x, o);
        sa.y += __shfl_xor_sync(0xffffffffu, sa.y, o);
        sa.z += __shfl_xor_sync(0xffffffffu, sa.z, o);
        sa.w += __shfl_xor_sync(0xffffffffu, sa.w, o);
    }

    // ---- epilogue: out[b][kg+j][4*lane..+3] += acc - sA_j * c  (red.v4) ----
    const float sa_arr[4] = {sa.x, sa.y, sa.z, sa.w};
    #pragma unroll
    for (int j = 0; j < 4; ++j) {
        int k = kg + j;
        float4 c = ((const float4*)cw)[k * 32 + lane];     // coalesced LDG.128
        float2 lo = unpack2(acc2[2 * j + 0]);
        float2 hi = unpack2(acc2[2 * j + 1]);
        float sj = sa_arr[j];
        red_add_v4(out + ((size_t)b * KK + k) * DD + 4 * lane,
                   fmaf(-sj, c.x, lo.x),
                   fmaf(-sj, c.y, lo.y),
                   fmaf(-sj, c.z, hi.x),
                   fmaf(-sj, c.w, hi.y));
    }
}

extern "C" void kernel_launch(void* const* d_in, const int* in_sizes, int n_in,
                              void* d_out, int out_size) {
    const float* x  = (const float*)d_in[0];   // [16,32,32,128]
    const float* cw = (const float*)d_in[1];   // [32,128]
    const float* sc = (const float*)d_in[2];   // [32]
    float* out = (float*)d_out;                // [16,32,128]

    cudaFuncSetAttribute(ev_encode_kernel,
                         cudaFuncAttributeMaxDynamicSharedMemorySize, SMEM_BYTES);

    // out is poisoned by the harness; REDs need zeros
    ev_zero_kernel<<<(BB * KK * DD / 4) / 256, 256>>>((float4*)out);
    ev_encode_kernel<<<NCHUNK, NTHREADS, SMEM_BYTES>>>(x, cw, sc, out);
}